// round 15
// baseline (speedup 1.0000x reference)
#include <cuda_runtime.h>
#include <cuda_bf16.h>
#include <cuda_fp16.h>
#include <math.h>
#include <stdint.h>

typedef __nv_bfloat16 bf16;

#define Bsz 64
#define CHN 512
#define TDm 256
#define NH 4
#define DHd 64
#define TLAT 1000
#define TQPAD 1024
#define TTXT 512
// 1/sqrt(TD)=0.0625 folded with log2(e): applied to Q at projection time
#define SCALE_L2E 0.09016844f

// ---------------- scratch (device globals; allocation-free) ----------------
__device__ bf16 g_xT[(size_t)Bsz * TQPAD * CHN];
__device__ bf16 g_tT[(size_t)Bsz * TTXT * TDm];
__device__ bf16 g_Qb[(size_t)Bsz * NH * TQPAD * DHd];    // pre-scaled by SCALE_L2E
__device__ bf16 g_Kb[(size_t)Bsz * NH * TTXT * DHd];
__device__ __half g_Vh[(size_t)Bsz * NH * DHd * TTXT];   // fp16 V (transposed)
__device__ bf16 g_Ob[(size_t)Bsz * TQPAD * TDm];
__device__ bf16 g_Wqb[TDm * CHN];
__device__ bf16 g_Wkb[TDm * TDm];
__device__ bf16 g_Wvb[TDm * TDm];
__device__ bf16 g_Wob[CHN * TDm];

// ---------------------------------------------------------------------------
__device__ __forceinline__ void mma_bf16(float c[4], const uint32_t a[4],
                                         const uint32_t b[2]) {
    asm volatile(
        "mma.sync.aligned.m16n8k16.row.col.f32.bf16.bf16.f32 "
        "{%0,%1,%2,%3}, {%4,%5,%6,%7}, {%8,%9}, {%0,%1,%2,%3};\n"
        : "+f"(c[0]), "+f"(c[1]), "+f"(c[2]), "+f"(c[3])
        : "r"(a[0]), "r"(a[1]), "r"(a[2]), "r"(a[3]), "r"(b[0]), "r"(b[1]));
}
__device__ __forceinline__ void mma_f16(float c[4], const uint32_t a[4],
                                        const uint32_t b[2]) {
    asm volatile(
        "mma.sync.aligned.m16n8k16.row.col.f32.f16.f16.f32 "
        "{%0,%1,%2,%3}, {%4,%5,%6,%7}, {%8,%9}, {%0,%1,%2,%3};\n"
        : "+f"(c[0]), "+f"(c[1]), "+f"(c[2]), "+f"(c[3])
        : "r"(a[0]), "r"(a[1]), "r"(a[2]), "r"(a[3]), "r"(b[0]), "r"(b[1]));
}
__device__ __forceinline__ uint32_t packbf2(float lo, float hi) {
    uint32_t r;
    asm("cvt.rn.bf16x2.f32 %0, %1, %2;" : "=r"(r) : "f"(hi), "f"(lo));
    return r;
}
__device__ __forceinline__ uint32_t packh2(float lo, float hi) {
    uint32_t r;
    asm("cvt.rn.f16x2.f32 %0, %1, %2;" : "=r"(r) : "f"(hi), "f"(lo));
    return r;
}
__device__ __forceinline__ uint32_t h2ex2(uint32_t v) {
    uint32_t r;
    asm("ex2.approx.f16x2 %0, %1;" : "=r"(r) : "r"(v));
    return r;
}
__device__ __forceinline__ void ldsm_x4(uint32_t r[4], const void* p) {
    uint32_t a = (uint32_t)__cvta_generic_to_shared(p);
    asm volatile(
        "ldmatrix.sync.aligned.m8n8.x4.shared.b16 {%0,%1,%2,%3}, [%4];"
        : "=r"(r[0]), "=r"(r[1]), "=r"(r[2]), "=r"(r[3]) : "r"(a));
}
__device__ __forceinline__ void cp_async16(void* dst, const void* src) {
    uint32_t d = (uint32_t)__cvta_generic_to_shared(dst);
    asm volatile("cp.async.ca.shared.global [%0], [%1], 16;" :: "r"(d), "l"(src));
}
__device__ __forceinline__ void cp_commit() {
    asm volatile("cp.async.commit_group;");
}
template <int N>
__device__ __forceinline__ void cp_wait() {
    asm volatile("cp.async.wait_group %0;" :: "n"(N));
}

// ---------------------------------------------------------------------------
// transpose+convert, vectorized stores (2 bf16 per STG.32)
// ---------------------------------------------------------------------------
__global__ void __launch_bounds__(256) transpose_bf(
    const float* __restrict__ in, int D1, int D2, int D2pad, int dst)
{
    __shared__ float tile[32][33];
    const int b = blockIdx.z;
    const int j0 = blockIdx.x * 32;
    const int i0 = blockIdx.y * 32;
    const int tx = threadIdx.x, ty = threadIdx.y;
    const float* inb = in + (size_t)b * D1 * D2;
#pragma unroll
    for (int p = 0; p < 4; p++) {
        int r = i0 + ty + p * 8;
        int j = j0 + tx;
        tile[ty + p * 8][tx] = (j < D2) ? inb[(size_t)r * D2 + j] : 0.f;
    }
    __syncthreads();
    bf16* out = (dst == 0) ? g_xT : g_tT;
    bf16* outb = out + (size_t)b * D2pad * D1;
    const int ix = (tx & 15) * 2;
    const int jq = (tx >> 4);
#pragma unroll
    for (int p = 0; p < 4; p++) {
        int jj = ty + p * 8 + jq * 16;
        int j = j0 + (jj & 31);
        *(uint32_t*)&outb[(size_t)j * D1 + i0 + ix] =
            packbf2(tile[ix][jj & 31], tile[ix + 1][jj & 31]);
    }
}

__global__ void __launch_bounds__(256) conv_weights(
    const float* __restrict__ Wq, const float* __restrict__ Wk,
    const float* __restrict__ Wv, const float* __restrict__ Wo)
{
    int i = blockIdx.x * 256 + threadIdx.x;
    if (i < TDm * CHN) g_Wqb[i] = __float2bfloat16(Wq[i]);
    if (i < TDm * TDm) {
        g_Wkb[i] = __float2bfloat16(Wk[i]);
        g_Wvb[i] = __float2bfloat16(Wv[i]);
    }
    if (i < CHN * TDm) g_Wob[i] = __float2bfloat16(Wo[i]);
}

// ---------------------------------------------------------------------------
// GEMM core 128x128: K chunks of 64, 2-stage cp.async, ONE sync per k-tile.
// ---------------------------------------------------------------------------
#define GEMM_SMEM 73728

__device__ __forceinline__ void gemm128x128(
    char* sm, const bf16* Ab, const bf16* Bb, int Kdim, int tid)
{
    bf16 (*As)[128][72] = (bf16(*)[128][72])sm;
    bf16 (*Bs)[128][72] = (bf16(*)[128][72])(sm + 2 * 128 * 72 * 2);
    float (*Cs)[133]    = (float(*)[133])sm;

    const int wid = tid >> 5, lane = tid & 31;
    const int g = lane >> 2, tig = lane & 3;
    const int m0 = (wid >> 1) * 32, n0 = (wid & 1) * 64;

    const int a_row = (lane & 7) + ((lane >> 3) & 1) * 8;
    const int a_col = (lane >> 4) * 8;
    const int b_row = ((lane >> 4) & 1) * 8 + (lane & 7);
    const int b_col = ((lane >> 3) & 1) * 8;

    const int fr = tid >> 3, fc8 = (tid & 7) * 8;
    const int KT = Kdim >> 6;

#pragma unroll
    for (int p = 0; p < 4; p++) {
        int r = fr + p * 32;
        cp_async16(&As[0][r][fc8], &Ab[(size_t)r * Kdim + fc8]);
        cp_async16(&Bs[0][r][fc8], &Bb[(size_t)r * Kdim + fc8]);
    }
    cp_commit();

    float acc[2][8][4] = {};

    for (int kt = 0; kt < KT; kt++) {
        int cur = kt & 1;
        cp_wait<0>();
        __syncthreads();
        if (kt + 1 < KT) {
            int nxt = cur ^ 1;
            int k0 = (kt + 1) << 6;
#pragma unroll
            for (int p = 0; p < 4; p++) {
                int r = fr + p * 32;
                cp_async16(&As[nxt][r][fc8], &Ab[(size_t)r * Kdim + k0 + fc8]);
                cp_async16(&Bs[nxt][r][fc8], &Bb[(size_t)r * Kdim + k0 + fc8]);
            }
            cp_commit();
        }

#pragma unroll
        for (int kc = 0; kc < 4; kc++) {
            uint32_t am[2][4];
            ldsm_x4(am[0], &As[cur][m0 + a_row][kc * 16 + a_col]);
            ldsm_x4(am[1], &As[cur][m0 + 16 + a_row][kc * 16 + a_col]);
#pragma unroll
            for (int np = 0; np < 4; np++) {
                uint32_t bb[4];
                ldsm_x4(bb, &Bs[cur][n0 + np * 16 + b_row][kc * 16 + b_col]);
                mma_bf16(acc[0][2 * np], am[0], bb);
                mma_bf16(acc[0][2 * np + 1], am[0], bb + 2);
                mma_bf16(acc[1][2 * np], am[1], bb);
                mma_bf16(acc[1][2 * np + 1], am[1], bb + 2);
            }
        }
    }
    __syncthreads();   // protect Cs overlay of As/Bs

#pragma unroll
    for (int ms = 0; ms < 2; ms++)
#pragma unroll
        for (int ns = 0; ns < 8; ns++) {
            int r = m0 + ms * 16 + g;
            int c = n0 + ns * 8 + 2 * tig;
            Cs[r][c]         = acc[ms][ns][0];
            Cs[r][c + 1]     = acc[ms][ns][1];
            Cs[r + 8][c]     = acc[ms][ns][2];
            Cs[r + 8][c + 1] = acc[ms][ns][3];
        }
    __syncthreads();
}

// ---------------------------------------------------------------------------
// Projection: CTA = 128 t x 2 heads. mode 0=Q(rope, pre-scaled) 1=K(rope)
// 2=V(f16, transposed)
// ---------------------------------------------------------------------------
__global__ void __launch_bounds__(256) proj_mma(
    const float* __restrict__ bias, const float* __restrict__ theta,
    const float* __restrict__ inc, int Mpad, int M, int Kdim,
    float inv_len, int mode)
{
    extern __shared__ __align__(16) char sm[];
    float (*Cs)[133] = (float(*)[133])sm;

    const int b = blockIdx.z;
    const int h0 = blockIdx.y * 2;
    const int t0 = blockIdx.x * 128;
    const int tid = threadIdx.x;

    const bf16* A = (mode == 0) ? g_xT : g_tT;
    const bf16* W = (mode == 0) ? g_Wqb : (mode == 1) ? g_Wkb : g_Wvb;
    const bf16* Ab = A + ((size_t)b * Mpad + t0) * Kdim;
    const bf16* Wb = W + (size_t)(h0 * 64) * Kdim;

    gemm128x128(sm, Ab, Wb, Kdim, tid);

    if (mode < 2) {
        const int th = tid >> 1;
        const int side = tid & 1;
        const int h = h0 + side;
        const int t = t0 + th;
        const float oscale = (mode == 0) ? SCALE_L2E : 1.f;
        bf16* orow = ((mode == 0) ? g_Qb : g_Kb) +
                     ((size_t)(b * NH + h) * Mpad + t) * 64;
        if (t < M) {
            float pos = inc[t] * inv_len;
            const float* bs = bias + h * 64;
            float o[64];
#pragma unroll
            for (int jj = 0; jj < 32; jj++) {
                float x1 = Cs[th][side * 64 + jj] + bs[jj];
                float x2 = Cs[th][side * 64 + 32 + jj] + bs[32 + jj];
                float sv, cv;
                __sincosf(pos * theta[jj], &sv, &cv);
                o[jj] = (x1 * cv - x2 * sv) * oscale;
                o[32 + jj] = (x1 * sv + x2 * cv) * oscale;
            }
            uint32_t pk[32];
#pragma unroll
            for (int m = 0; m < 32; m++) pk[m] = packbf2(o[2 * m], o[2 * m + 1]);
#pragma unroll
            for (int q = 0; q < 8; q++)
                *(uint4*)&orow[q * 8] = *(uint4*)&pk[q * 4];
        } else {
            uint4 z = {0, 0, 0, 0};
#pragma unroll
            for (int q = 0; q < 8; q++) *(uint4*)&orow[q * 8] = z;
        }
    } else {
        const int th = tid & 127;
        const int cg = tid >> 7;
        __half* outp = g_Vh + (size_t)b * NH * 64 * Mpad;
#pragma unroll
        for (int p = 0; p < 64; p++) {
            int cl = cg + p * 2;
            int d = h0 * 64 + cl;
            outp[(size_t)d * Mpad + t0 + th] =
                __float2half(Cs[th][cl] + bias[d]);
        }
    }
}

// ---------------------------------------------------------------------------
// Output projection (R10): CTA 128 t x 64 c; single-sync; +res/bias/mask.
// ---------------------------------------------------------------------------
#define OPROJ_SMEM 55296

__global__ void __launch_bounds__(256) oproj_mma(
    const float* __restrict__ x, const float* __restrict__ bo,
    const float* __restrict__ lmask, float* __restrict__ out)
{
    extern __shared__ __align__(16) char smraw[];
    bf16 (*As)[128][72] = (bf16(*)[128][72])smraw;
    bf16 (*Bs)[64][72]  = (bf16(*)[64][72])(smraw + 2 * 128 * 72 * 2);
    float (*Cs)[65]     = (float(*)[65])smraw;

    const int b = blockIdx.z;
    const int t0 = blockIdx.x * 128;
    const int c0 = blockIdx.y * 64;
    const int tid = threadIdx.x;
    const int wid = tid >> 5, lane = tid & 31;
    const int g = lane >> 2, tig = lane & 3;
    const int m0 = (wid >> 1) * 32, n0 = (wid & 1) * 32;

    const int a_row = (lane & 7) + ((lane >> 3) & 1) * 8;
    const int a_col = (lane >> 4) * 8;
    const int b_row = ((lane >> 4) & 1) * 8 + (lane & 7);
    const int b_col = ((lane >> 3) & 1) * 8;

    const bf16* Ab = g_Ob + ((size_t)b * TQPAD + t0) * TDm;
    const bf16* Wb = g_Wob + (size_t)c0 * TDm;

    const int ar = tid >> 3, ac8 = (tid & 7) * 8;
    const int KT = TDm >> 6;

#pragma unroll
    for (int p = 0; p < 4; p++)
        cp_async16(&As[0][ar + p * 32][ac8], &Ab[(size_t)(ar + p * 32) * TDm + ac8]);
#pragma unroll
    for (int p = 0; p < 2; p++)
        cp_async16(&Bs[0][ar + p * 32][ac8], &Wb[(size_t)(ar + p * 32) * TDm + ac8]);
    cp_commit();

    float acc[2][4][4] = {};

    for (int kt = 0; kt < KT; kt++) {
        int cur = kt & 1;
        cp_wait<0>();
        __syncthreads();
        if (kt + 1 < KT) {
            int nxt = cur ^ 1;
            int k0 = (kt + 1) << 6;
#pragma unroll
            for (int p = 0; p < 4; p++)
                cp_async16(&As[nxt][ar + p * 32][ac8],
                           &Ab[(size_t)(ar + p * 32) * TDm + k0 + ac8]);
#pragma unroll
            for (int p = 0; p < 2; p++)
                cp_async16(&Bs[nxt][ar + p * 32][ac8],
                           &Wb[(size_t)(ar + p * 32) * TDm + k0 + ac8]);
            cp_commit();
        }

#pragma unroll
        for (int kc = 0; kc < 4; kc++) {
            uint32_t am[2][4];
            ldsm_x4(am[0], &As[cur][m0 + a_row][kc * 16 + a_col]);
            ldsm_x4(am[1], &As[cur][m0 + 16 + a_row][kc * 16 + a_col]);
#pragma unroll
            for (int np = 0; np < 2; np++) {
                uint32_t bb[4];
                ldsm_x4(bb, &Bs[cur][n0 + np * 16 + b_row][kc * 16 + b_col]);
                mma_bf16(acc[0][2 * np], am[0], bb);
                mma_bf16(acc[0][2 * np + 1], am[0], bb + 2);
                mma_bf16(acc[1][2 * np], am[1], bb);
                mma_bf16(acc[1][2 * np + 1], am[1], bb + 2);
            }
        }
    }
    __syncthreads();   // protect Cs overlay

#pragma unroll
    for (int ms = 0; ms < 2; ms++)
#pragma unroll
        for (int ns = 0; ns < 4; ns++) {
            int r = m0 + ms * 16 + g;
            int c = n0 + ns * 8 + 2 * tig;
            Cs[r][c]         = acc[ms][ns][0];
            Cs[r][c + 1]     = acc[ms][ns][1];
            Cs[r + 8][c]     = acc[ms][ns][2];
            Cs[r + 8][c + 1] = acc[ms][ns][3];
        }
    __syncthreads();

    int tt = tid & 127;
    int t = t0 + tt;
    if (t < TLAT) {
        float lm = lmask[(size_t)b * TLAT + t];
        int cb = (tid >> 7) * 32;
#pragma unroll
        for (int p = 0; p < 32; p++) {
            int cc = cb + p;
            int c = c0 + cc;
            size_t idx = ((size_t)b * CHN + c) * TLAT + t;
            out[idx] = (x[idx] + bo[c] + Cs[tt][cc]) * lm;
        }
    }
}

// ---------------------------------------------------------------------------
// FA attention (R12 structure) with 3-STAGE ring buffer, distance-2 prefetch,
// cp_wait<1> (fill gets TWO compute phases to land; newest fill never drained).
// Static-max softmax, f16x2 ex2, f16 PV, l via ones-MMA.
// smem: Qs 18432 + Ks[3] 27648 + Vs[3] 27648 + Ms 2048 = 75776 B -> 2 CTAs/SM
// ---------------------------------------------------------------------------
#define ATT_SMEM (18432 + 3 * 9216 + 3 * 9216 + 2048)

__global__ void __launch_bounds__(256) attn_mma(const int* __restrict__ tmask)
{
    extern __shared__ __align__(16) char smraw[];
    bf16 (*Qs)[72]        = (bf16(*)[72])smraw;
    bf16 (*Ks)[64][72]    = (bf16(*)[64][72])(smraw + 18432);
    __half (*Vs)[64][72]  = (__half(*)[64][72])(smraw + 18432 + 3 * 9216);
    float* Ms             = (float*)(smraw + 18432 + 6 * 9216);

    const int qt = blockIdx.x, h = blockIdx.y, b = blockIdx.z;
    const int tid = threadIdx.x;
    const int wid = tid >> 5, lane = tid & 31;
    const int g = lane >> 2, tig = lane & 3;
    const int r0 = wid * 16;

    const int a_row = (lane & 7) + ((lane >> 3) & 1) * 8;
    const int a_col = (lane >> 4) * 8;
    const int b_row = ((lane >> 4) & 1) * 8 + (lane & 7);
    const int b_col = ((lane >> 3) & 1) * 8;

    const bf16* Qg = g_Qb + ((size_t)(b * NH + h) * TQPAD + qt * 128) * 64;
    const bf16* Kg = g_Kb + (size_t)(b * NH + h) * TTXT * 64;
    const __half* Vg = g_Vh + (size_t)(b * NH + h) * 64 * TTXT;

    const int ar = tid >> 3, ac8 = (tid & 7) * 8;
    const float NEGINF = __int_as_float(0xff800000);
    const int NK = TTXT / 64;   // 8

    // prologue: group0 = Q + K/V tile 0; group1 = K/V tile 1
#pragma unroll
    for (int p = 0; p < 4; p++)
        cp_async16(&Qs[ar + p * 32][ac8], &Qg[(size_t)(ar + p * 32) * 64 + ac8]);
#pragma unroll
    for (int p = 0; p < 2; p++) {
        int r = ar + p * 32;
        cp_async16(&Ks[0][r][ac8], &Kg[(size_t)r * 64 + ac8]);
        cp_async16(&Vs[0][r][ac8], &Vg[(size_t)r * TTXT + ac8]);
    }
    cp_commit();
#pragma unroll
    for (int p = 0; p < 2; p++) {
        int r = ar + p * 32;
        cp_async16(&Ks[1][r][ac8], &Kg[(size_t)(64 + r) * 64 + ac8]);
        cp_async16(&Vs[1][r][ac8], &Vg[(size_t)r * TTXT + 64 + ac8]);
    }
    cp_commit();
#pragma unroll
    for (int p = 0; p < 2; p++)
        Ms[tid + p * 256] =
            (tmask[b * TTXT + tid + p * 256] != 0) ? 0.f : NEGINF;

    const uint32_t bone = (g == 0) ? 0x3C003C00u : 0u;
    uint32_t b_ones[2] = {bone, bone};

    float oc[8][4] = {};
    float oc_l[4] = {};
    uint32_t qa[4][4];

    for (int kt = 0; kt < NK; kt++) {
        int cur = kt % 3;
        cp_wait<1>();      // fill(kt) done; fill(kt+1) may still be in flight
        __syncthreads();   // visibility; prefetch target (kt+2)%3 reads done at kt-1

        if (kt == 0) {
#pragma unroll
            for (int kc = 0; kc < 4; kc++)
                ldsm_x4(qa[kc], &Qs[r0 + a_row][kc * 16 + a_col]);
        }

        if (kt + 2 < NK) {
            int nxt = (kt + 2) % 3;
            int kb = (kt + 2) * 64;
#pragma unroll
            for (int p = 0; p < 2; p++) {
                int r = ar + p * 32;
                cp_async16(&Ks[nxt][r][ac8], &Kg[(size_t)(kb + r) * 64 + ac8]);
                cp_async16(&Vs[nxt][r][ac8], &Vg[(size_t)r * TTXT + kb + ac8]);
            }
            cp_commit();
        } else {
            cp_commit();   // keep group count uniform so wait<1> semantics hold
        }

        // S = Q K^T  (already in log2 domain — Q pre-scaled)
        float sc[8][4] = {};
#pragma unroll
        for (int kc = 0; kc < 4; kc++) {
#pragma unroll
            for (int np = 0; np < 4; np++) {
                uint32_t bb[4];
                ldsm_x4(bb, &Ks[cur][np * 16 + b_row][kc * 16 + b_col]);
                mma_bf16(sc[2 * np], qa[kc], bb);
                mma_bf16(sc[2 * np + 1], qa[kc], bb + 2);
            }
        }

        // p = 2^(s + maskbias); masked -> -inf -> 0. Packs as f16 A-frag.
        const float* Mt = Ms + kt * 64;
        uint32_t pa[4][4];
#pragma unroll
        for (int kc = 0; kc < 4; kc++) {
            float mbA0 = Mt[kc * 16 + 2 * tig], mbA1 = Mt[kc * 16 + 2 * tig + 1];
            float mbB0 = Mt[kc * 16 + 8 + 2 * tig], mbB1 = Mt[kc * 16 + 8 + 2 * tig + 1];
            pa[kc][0] = h2ex2(packh2(sc[2 * kc][0] + mbA0, sc[2 * kc][1] + mbA1));
            pa[kc][1] = h2ex2(packh2(sc[2 * kc][2] + mbA0, sc[2 * kc][3] + mbA1));
            pa[kc][2] = h2ex2(packh2(sc[2 * kc + 1][0] + mbB0, sc[2 * kc + 1][1] + mbB1));
            pa[kc][3] = h2ex2(packh2(sc[2 * kc + 1][2] + mbB0, sc[2 * kc + 1][3] + mbB1));
        }

        // O += P V  (f16 mma; V^T in smem);  l += P . 1
#pragma unroll
        for (int kc = 0; kc < 4; kc++) {
#pragma unroll
            for (int np = 0; np < 4; np++) {
                uint32_t vb[4];
                ldsm_x4(vb, &Vs[cur][np * 16 + b_row][kc * 16 + b_col]);
                mma_f16(oc[2 * np], pa[kc], vb);
                mma_f16(oc[2 * np + 1], pa[kc], vb + 2);
            }
            mma_f16(oc_l, pa[kc], b_ones);
        }
    }

    float lv0 = __shfl_sync(~0u, oc_l[0], lane & ~3);
    float lv1 = __shfl_sync(~0u, oc_l[2], lane & ~3);
    float inv0 = 1.f / lv0, inv1 = 1.f / lv1;
    int tg = qt * 128 + r0 + g;
    bf16* Ob = g_Ob + (size_t)b * TQPAD * TDm + h * 64;
#pragma unroll
    for (int ns = 0; ns < 8; ns++) {
        int c = ns * 8 + 2 * tig;
        *(uint32_t*)&Ob[(size_t)tg * TDm + c] =
            packbf2(oc[ns][0] * inv0, oc[ns][1] * inv0);
        *(uint32_t*)&Ob[(size_t)(tg + 8) * TDm + c] =
            packbf2(oc[ns][2] * inv1, oc[ns][3] * inv1);
    }
}

// ---------------------------------------------------------------------------
extern "C" void kernel_launch(void* const* d_in, const int* in_sizes, int n_in,
                              void* d_out, int out_size)
{
    const float* x     = (const float*)d_in[0];
    const float* temb  = (const float*)d_in[1];
    const float* lmask = (const float*)d_in[2];
    const int*   tmask = (const int*)d_in[3];
    const float* Wq    = (const float*)d_in[4];
    const float* bq    = (const float*)d_in[5];
    const float* Wk    = (const float*)d_in[6];
    const float* bk    = (const float*)d_in[7];
    const float* Wv    = (const float*)d_in[8];
    const float* bv    = (const float*)d_in[9];
    const float* Wo    = (const float*)d_in[10];
    const float* bo    = (const float*)d_in[11];
    const float* theta = (const float*)d_in[12];
    const float* inc   = (const float*)d_in[13];
    float* out = (float*)d_out;

    cudaFuncSetAttribute(proj_mma, cudaFuncAttributeMaxDynamicSharedMemorySize,
                         GEMM_SMEM);
    cudaFuncSetAttribute(oproj_mma, cudaFuncAttributeMaxDynamicSharedMemorySize,
                         OPROJ_SMEM);
    cudaFuncSetAttribute(attn_mma, cudaFuncAttributeMaxDynamicSharedMemorySize,
                         ATT_SMEM);

    transpose_bf<<<dim3(TQPAD / 32, CHN / 32, Bsz), dim3(32, 8)>>>(
        x, CHN, TLAT, TQPAD, 0);
    transpose_bf<<<dim3(TTXT / 32, TDm / 32, Bsz), dim3(32, 8)>>>(
        temb, TDm, TTXT, TTXT, 1);
    conv_weights<<<(TDm * CHN + 255) / 256, 256>>>(Wq, Wk, Wv, Wo);

    proj_mma<<<dim3(TQPAD / 128, NH / 2, Bsz), 256, GEMM_SMEM>>>(
        bq, theta, inc, TQPAD, TLAT, CHN, 1.f / (float)TLAT, 0);
    proj_mma<<<dim3(TTXT / 128, NH / 2, Bsz), 256, GEMM_SMEM>>>(
        bk, theta, inc, TTXT, TTXT, TDm, 1.f / (float)TTXT, 1);
    proj_mma<<<dim3(TTXT / 128, NH / 2, Bsz), 256, GEMM_SMEM>>>(
        bv, theta, inc, TTXT, TTXT, TDm, 1.f / (float)TTXT, 2);

    attn_mma<<<dim3(TQPAD / 128, NH, Bsz), 256, ATT_SMEM>>>(tmask);

    oproj_mma<<<dim3(TQPAD / 128, CHN / 64, Bsz), 256, OPROJ_SMEM>>>(
        x, bo, lmask, out);
}

// round 16
// speedup vs baseline: 1.5046x; 1.5046x over previous
#include <cuda_runtime.h>
#include <cuda_bf16.h>
#include <cuda_fp16.h>
#include <math.h>
#include <stdint.h>

typedef __nv_bfloat16 bf16;

#define Bsz 64
#define CHN 512
#define TDm 256
#define NH 4
#define DHd 64
#define TLAT 1000
#define TQPAD 1024
#define TTXT 512
// 1/sqrt(TD)=0.0625 folded with log2(e): applied to Q at projection time
#define SCALE_L2E 0.09016844f

// ---------------- scratch (device globals; allocation-free) ----------------
__device__ bf16 g_xT[(size_t)Bsz * TQPAD * CHN];
__device__ bf16 g_tT[(size_t)Bsz * TTXT * TDm];
__device__ bf16 g_Qb[(size_t)Bsz * NH * TQPAD * DHd];    // pre-scaled by SCALE_L2E
__device__ bf16 g_Kb[(size_t)Bsz * NH * TTXT * DHd];
__device__ __half g_Vh[(size_t)Bsz * NH * DHd * TTXT];   // fp16 V (transposed)
__device__ bf16 g_Ob[(size_t)Bsz * TQPAD * TDm];
__device__ bf16 g_Wqb[TDm * CHN];
__device__ bf16 g_Wkb[TDm * TDm];
__device__ bf16 g_Wvb[TDm * TDm];
__device__ bf16 g_Wob[CHN * TDm];

// ---------------------------------------------------------------------------
__device__ __forceinline__ void mma_bf16(float c[4], const uint32_t a[4],
                                         const uint32_t b[2]) {
    asm volatile(
        "mma.sync.aligned.m16n8k16.row.col.f32.bf16.bf16.f32 "
        "{%0,%1,%2,%3}, {%4,%5,%6,%7}, {%8,%9}, {%0,%1,%2,%3};\n"
        : "+f"(c[0]), "+f"(c[1]), "+f"(c[2]), "+f"(c[3])
        : "r"(a[0]), "r"(a[1]), "r"(a[2]), "r"(a[3]), "r"(b[0]), "r"(b[1]));
}
__device__ __forceinline__ void mma_f16(float c[4], const uint32_t a[4],
                                        const uint32_t b[2]) {
    asm volatile(
        "mma.sync.aligned.m16n8k16.row.col.f32.f16.f16.f32 "
        "{%0,%1,%2,%3}, {%4,%5,%6,%7}, {%8,%9}, {%0,%1,%2,%3};\n"
        : "+f"(c[0]), "+f"(c[1]), "+f"(c[2]), "+f"(c[3])
        : "r"(a[0]), "r"(a[1]), "r"(a[2]), "r"(a[3]), "r"(b[0]), "r"(b[1]));
}
__device__ __forceinline__ uint32_t packbf2(float lo, float hi) {
    uint32_t r;
    asm("cvt.rn.bf16x2.f32 %0, %1, %2;" : "=r"(r) : "f"(hi), "f"(lo));
    return r;
}
__device__ __forceinline__ uint32_t packh2(float lo, float hi) {
    uint32_t r;
    asm("cvt.rn.f16x2.f32 %0, %1, %2;" : "=r"(r) : "f"(hi), "f"(lo));
    return r;
}
__device__ __forceinline__ uint32_t h2ex2(uint32_t v) {
    uint32_t r;
    asm("ex2.approx.f16x2 %0, %1;" : "=r"(r) : "r"(v));
    return r;
}
__device__ __forceinline__ void ldsm_x4(uint32_t r[4], const void* p) {
    uint32_t a = (uint32_t)__cvta_generic_to_shared(p);
    asm volatile(
        "ldmatrix.sync.aligned.m8n8.x4.shared.b16 {%0,%1,%2,%3}, [%4];"
        : "=r"(r[0]), "=r"(r[1]), "=r"(r[2]), "=r"(r[3]) : "r"(a));
}
__device__ __forceinline__ void cp_async16(void* dst, const void* src) {
    uint32_t d = (uint32_t)__cvta_generic_to_shared(dst);
    asm volatile("cp.async.ca.shared.global [%0], [%1], 16;" :: "r"(d), "l"(src));
}
__device__ __forceinline__ void cp_commit() {
    asm volatile("cp.async.commit_group;");
}
template <int N>
__device__ __forceinline__ void cp_wait() {
    asm volatile("cp.async.wait_group %0;" :: "n"(N));
}

// ---------------------------------------------------------------------------
// transpose+convert, vectorized stores (2 bf16 per STG.32)
// ---------------------------------------------------------------------------
__global__ void __launch_bounds__(256) transpose_bf(
    const float* __restrict__ in, int D1, int D2, int D2pad, int dst)
{
    __shared__ float tile[32][33];
    const int b = blockIdx.z;
    const int j0 = blockIdx.x * 32;
    const int i0 = blockIdx.y * 32;
    const int tx = threadIdx.x, ty = threadIdx.y;
    const float* inb = in + (size_t)b * D1 * D2;
#pragma unroll
    for (int p = 0; p < 4; p++) {
        int r = i0 + ty + p * 8;
        int j = j0 + tx;
        tile[ty + p * 8][tx] = (j < D2) ? inb[(size_t)r * D2 + j] : 0.f;
    }
    __syncthreads();
    bf16* out = (dst == 0) ? g_xT : g_tT;
    bf16* outb = out + (size_t)b * D2pad * D1;
    const int ix = (tx & 15) * 2;
    const int jq = (tx >> 4);
#pragma unroll
    for (int p = 0; p < 4; p++) {
        int jj = ty + p * 8 + jq * 16;
        int j = j0 + (jj & 31);
        *(uint32_t*)&outb[(size_t)j * D1 + i0 + ix] =
            packbf2(tile[ix][jj & 31], tile[ix + 1][jj & 31]);
    }
}

__global__ void __launch_bounds__(256) conv_weights(
    const float* __restrict__ Wq, const float* __restrict__ Wk,
    const float* __restrict__ Wv, const float* __restrict__ Wo)
{
    int i = blockIdx.x * 256 + threadIdx.x;
    if (i < TDm * CHN) g_Wqb[i] = __float2bfloat16(Wq[i]);
    if (i < TDm * TDm) {
        g_Wkb[i] = __float2bfloat16(Wk[i]);
        g_Wvb[i] = __float2bfloat16(Wv[i]);
    }
    if (i < CHN * TDm) g_Wob[i] = __float2bfloat16(Wo[i]);
}

// ---------------------------------------------------------------------------
// GEMM core 128x128: K chunks of 64, 2-stage cp.async, ONE sync per k-tile.
// ---------------------------------------------------------------------------
#define GEMM_SMEM 73728

__device__ __forceinline__ void gemm128x128(
    char* sm, const bf16* Ab, const bf16* Bb, int Kdim, int tid)
{
    bf16 (*As)[128][72] = (bf16(*)[128][72])sm;
    bf16 (*Bs)[128][72] = (bf16(*)[128][72])(sm + 2 * 128 * 72 * 2);
    float (*Cs)[133]    = (float(*)[133])sm;

    const int wid = tid >> 5, lane = tid & 31;
    const int g = lane >> 2, tig = lane & 3;
    const int m0 = (wid >> 1) * 32, n0 = (wid & 1) * 64;

    const int a_row = (lane & 7) + ((lane >> 3) & 1) * 8;
    const int a_col = (lane >> 4) * 8;
    const int b_row = ((lane >> 4) & 1) * 8 + (lane & 7);
    const int b_col = ((lane >> 3) & 1) * 8;

    const int fr = tid >> 3, fc8 = (tid & 7) * 8;
    const int KT = Kdim >> 6;

#pragma unroll
    for (int p = 0; p < 4; p++) {
        int r = fr + p * 32;
        cp_async16(&As[0][r][fc8], &Ab[(size_t)r * Kdim + fc8]);
        cp_async16(&Bs[0][r][fc8], &Bb[(size_t)r * Kdim + fc8]);
    }
    cp_commit();

    float acc[2][8][4] = {};

    for (int kt = 0; kt < KT; kt++) {
        int cur = kt & 1;
        cp_wait<0>();
        __syncthreads();
        if (kt + 1 < KT) {
            int nxt = cur ^ 1;
            int k0 = (kt + 1) << 6;
#pragma unroll
            for (int p = 0; p < 4; p++) {
                int r = fr + p * 32;
                cp_async16(&As[nxt][r][fc8], &Ab[(size_t)r * Kdim + k0 + fc8]);
                cp_async16(&Bs[nxt][r][fc8], &Bb[(size_t)r * Kdim + k0 + fc8]);
            }
            cp_commit();
        }

#pragma unroll
        for (int kc = 0; kc < 4; kc++) {
            uint32_t am[2][4];
            ldsm_x4(am[0], &As[cur][m0 + a_row][kc * 16 + a_col]);
            ldsm_x4(am[1], &As[cur][m0 + 16 + a_row][kc * 16 + a_col]);
#pragma unroll
            for (int np = 0; np < 4; np++) {
                uint32_t bb[4];
                ldsm_x4(bb, &Bs[cur][n0 + np * 16 + b_row][kc * 16 + b_col]);
                mma_bf16(acc[0][2 * np], am[0], bb);
                mma_bf16(acc[0][2 * np + 1], am[0], bb + 2);
                mma_bf16(acc[1][2 * np], am[1], bb);
                mma_bf16(acc[1][2 * np + 1], am[1], bb + 2);
            }
        }
    }
    __syncthreads();   // protect Cs overlay of As/Bs

#pragma unroll
    for (int ms = 0; ms < 2; ms++)
#pragma unroll
        for (int ns = 0; ns < 8; ns++) {
            int r = m0 + ms * 16 + g;
            int c = n0 + ns * 8 + 2 * tig;
            Cs[r][c]         = acc[ms][ns][0];
            Cs[r][c + 1]     = acc[ms][ns][1];
            Cs[r + 8][c]     = acc[ms][ns][2];
            Cs[r + 8][c + 1] = acc[ms][ns][3];
        }
    __syncthreads();
}

// ---------------------------------------------------------------------------
// Projection: CTA = 128 t x 2 heads. mode 0=Q(rope, pre-scaled) 1=K(rope)
// 2=V(f16, transposed)
// ---------------------------------------------------------------------------
__global__ void __launch_bounds__(256) proj_mma(
    const float* __restrict__ bias, const float* __restrict__ theta,
    const float* __restrict__ inc, int Mpad, int M, int Kdim,
    float inv_len, int mode)
{
    extern __shared__ __align__(16) char sm[];
    float (*Cs)[133] = (float(*)[133])sm;

    const int b = blockIdx.z;
    const int h0 = blockIdx.y * 2;
    const int t0 = blockIdx.x * 128;
    const int tid = threadIdx.x;

    const bf16* A = (mode == 0) ? g_xT : g_tT;
    const bf16* W = (mode == 0) ? g_Wqb : (mode == 1) ? g_Wkb : g_Wvb;
    const bf16* Ab = A + ((size_t)b * Mpad + t0) * Kdim;
    const bf16* Wb = W + (size_t)(h0 * 64) * Kdim;

    gemm128x128(sm, Ab, Wb, Kdim, tid);

    if (mode < 2) {
        const int th = tid >> 1;
        const int side = tid & 1;
        const int h = h0 + side;
        const int t = t0 + th;
        const float oscale = (mode == 0) ? SCALE_L2E : 1.f;
        bf16* orow = ((mode == 0) ? g_Qb : g_Kb) +
                     ((size_t)(b * NH + h) * Mpad + t) * 64;
        if (t < M) {
            float pos = inc[t] * inv_len;
            const float* bs = bias + h * 64;
            float o[64];
#pragma unroll
            for (int jj = 0; jj < 32; jj++) {
                float x1 = Cs[th][side * 64 + jj] + bs[jj];
                float x2 = Cs[th][side * 64 + 32 + jj] + bs[32 + jj];
                float sv, cv;
                __sincosf(pos * theta[jj], &sv, &cv);
                o[jj] = (x1 * cv - x2 * sv) * oscale;
                o[32 + jj] = (x1 * sv + x2 * cv) * oscale;
            }
            uint32_t pk[32];
#pragma unroll
            for (int m = 0; m < 32; m++) pk[m] = packbf2(o[2 * m], o[2 * m + 1]);
#pragma unroll
            for (int q = 0; q < 8; q++)
                *(uint4*)&orow[q * 8] = *(uint4*)&pk[q * 4];
        } else {
            uint4 z = {0, 0, 0, 0};
#pragma unroll
            for (int q = 0; q < 8; q++) *(uint4*)&orow[q * 8] = z;
        }
    } else {
        const int th = tid & 127;
        const int cg = tid >> 7;
        __half* outp = g_Vh + (size_t)b * NH * 64 * Mpad;
#pragma unroll
        for (int p = 0; p < 64; p++) {
            int cl = cg + p * 2;
            int d = h0 * 64 + cl;
            outp[(size_t)d * Mpad + t0 + th] =
                __float2half(Cs[th][cl] + bias[d]);
        }
    }
}

// ---------------------------------------------------------------------------
// Output projection (R10): CTA 128 t x 64 c; single-sync; +res/bias/mask.
// ---------------------------------------------------------------------------
#define OPROJ_SMEM 55296

__global__ void __launch_bounds__(256) oproj_mma(
    const float* __restrict__ x, const float* __restrict__ bo,
    const float* __restrict__ lmask, float* __restrict__ out)
{
    extern __shared__ __align__(16) char smraw[];
    bf16 (*As)[128][72] = (bf16(*)[128][72])smraw;
    bf16 (*Bs)[64][72]  = (bf16(*)[64][72])(smraw + 2 * 128 * 72 * 2);
    float (*Cs)[65]     = (float(*)[65])smraw;

    const int b = blockIdx.z;
    const int t0 = blockIdx.x * 128;
    const int c0 = blockIdx.y * 64;
    const int tid = threadIdx.x;
    const int wid = tid >> 5, lane = tid & 31;
    const int g = lane >> 2, tig = lane & 3;
    const int m0 = (wid >> 1) * 32, n0 = (wid & 1) * 32;

    const int a_row = (lane & 7) + ((lane >> 3) & 1) * 8;
    const int a_col = (lane >> 4) * 8;
    const int b_row = ((lane >> 4) & 1) * 8 + (lane & 7);
    const int b_col = ((lane >> 3) & 1) * 8;

    const bf16* Ab = g_Ob + ((size_t)b * TQPAD + t0) * TDm;
    const bf16* Wb = g_Wob + (size_t)c0 * TDm;

    const int ar = tid >> 3, ac8 = (tid & 7) * 8;
    const int KT = TDm >> 6;

#pragma unroll
    for (int p = 0; p < 4; p++)
        cp_async16(&As[0][ar + p * 32][ac8], &Ab[(size_t)(ar + p * 32) * TDm + ac8]);
#pragma unroll
    for (int p = 0; p < 2; p++)
        cp_async16(&Bs[0][ar + p * 32][ac8], &Wb[(size_t)(ar + p * 32) * TDm + ac8]);
    cp_commit();

    float acc[2][4][4] = {};

    for (int kt = 0; kt < KT; kt++) {
        int cur = kt & 1;
        cp_wait<0>();
        __syncthreads();
        if (kt + 1 < KT) {
            int nxt = cur ^ 1;
            int k0 = (kt + 1) << 6;
#pragma unroll
            for (int p = 0; p < 4; p++)
                cp_async16(&As[nxt][ar + p * 32][ac8],
                           &Ab[(size_t)(ar + p * 32) * TDm + k0 + ac8]);
#pragma unroll
            for (int p = 0; p < 2; p++)
                cp_async16(&Bs[nxt][ar + p * 32][ac8],
                           &Wb[(size_t)(ar + p * 32) * TDm + k0 + ac8]);
            cp_commit();
        }

#pragma unroll
        for (int kc = 0; kc < 4; kc++) {
            uint32_t am[2][4];
            ldsm_x4(am[0], &As[cur][m0 + a_row][kc * 16 + a_col]);
            ldsm_x4(am[1], &As[cur][m0 + 16 + a_row][kc * 16 + a_col]);
#pragma unroll
            for (int np = 0; np < 2; np++) {
                uint32_t bb[4];
                ldsm_x4(bb, &Bs[cur][n0 + np * 16 + b_row][kc * 16 + b_col]);
                mma_bf16(acc[0][2 * np], am[0], bb);
                mma_bf16(acc[0][2 * np + 1], am[0], bb + 2);
                mma_bf16(acc[1][2 * np], am[1], bb);
                mma_bf16(acc[1][2 * np + 1], am[1], bb + 2);
            }
        }
    }
    __syncthreads();   // protect Cs overlay

#pragma unroll
    for (int ms = 0; ms < 2; ms++)
#pragma unroll
        for (int ns = 0; ns < 4; ns++) {
            int r = m0 + ms * 16 + g;
            int c = n0 + ns * 8 + 2 * tig;
            Cs[r][c]         = acc[ms][ns][0];
            Cs[r][c + 1]     = acc[ms][ns][1];
            Cs[r + 8][c]     = acc[ms][ns][2];
            Cs[r + 8][c + 1] = acc[ms][ns][3];
        }
    __syncthreads();

    int tt = tid & 127;
    int t = t0 + tt;
    if (t < TLAT) {
        float lm = lmask[(size_t)b * TLAT + t];
        int cb = (tid >> 7) * 32;
#pragma unroll
        for (int p = 0; p < 32; p++) {
            int cc = cb + p;
            int c = c0 + cc;
            size_t idx = ((size_t)b * CHN + c) * TLAT + t;
            out[idx] = (x[idx] + bo[c] + Cs[tt][cc]) * lm;
        }
    }
}

// ---------------------------------------------------------------------------
// FA attention (R12 champion): 2-stage cp.async, single sync per k-tile,
// static-max softmax (p = 2^(s + maskbias) directly; Q pre-scaled by
// SCALE_L2E), f16x2 ex2, f16 PV, l via ones-column MMA.
// ---------------------------------------------------------------------------
#define ATT_SMEM ((128 + 256) * 72 * 2 + 512 * 4)

__global__ void __launch_bounds__(256) attn_mma(const int* __restrict__ tmask)
{
    extern __shared__ __align__(16) char smraw[];
    bf16 (*Qs)[72]        = (bf16(*)[72])smraw;
    bf16 (*Ks)[64][72]    = (bf16(*)[64][72])(smraw + 128 * 72 * 2);
    __half (*Vs)[64][72]  = (__half(*)[64][72])(smraw + (128 + 128) * 72 * 2);
    float* Ms             = (float*)(smraw + (128 + 256) * 72 * 2);

    const int qt = blockIdx.x, h = blockIdx.y, b = blockIdx.z;
    const int tid = threadIdx.x;
    const int wid = tid >> 5, lane = tid & 31;
    const int g = lane >> 2, tig = lane & 3;
    const int r0 = wid * 16;

    const int a_row = (lane & 7) + ((lane >> 3) & 1) * 8;
    const int a_col = (lane >> 4) * 8;
    const int b_row = ((lane >> 4) & 1) * 8 + (lane & 7);
    const int b_col = ((lane >> 3) & 1) * 8;

    const bf16* Qg = g_Qb + ((size_t)(b * NH + h) * TQPAD + qt * 128) * 64;
    const bf16* Kg = g_Kb + (size_t)(b * NH + h) * TTXT * 64;
    const __half* Vg = g_Vh + (size_t)(b * NH + h) * 64 * TTXT;

    const int ar = tid >> 3, ac8 = (tid & 7) * 8;
    const float NEGINF = __int_as_float(0xff800000);

#pragma unroll
    for (int p = 0; p < 4; p++)
        cp_async16(&Qs[ar + p * 32][ac8], &Qg[(size_t)(ar + p * 32) * 64 + ac8]);
#pragma unroll
    for (int p = 0; p < 2; p++) {
        int r = ar + p * 32;
        cp_async16(&Ks[0][r][ac8], &Kg[(size_t)r * 64 + ac8]);
        cp_async16(&Vs[0][r][ac8], &Vg[(size_t)r * TTXT + ac8]);
    }
    cp_commit();
#pragma unroll
    for (int p = 0; p < 2; p++)
        Ms[tid + p * 256] =
            (tmask[b * TTXT + tid + p * 256] != 0) ? 0.f : NEGINF;

    const uint32_t bone = (g == 0) ? 0x3C003C00u : 0u;
    uint32_t b_ones[2] = {bone, bone};

    float oc[8][4] = {};
    float oc_l[4] = {};
    uint32_t qa[4][4];

    for (int kt = 0; kt < TTXT / 64; kt++) {
        int cur = kt & 1;
        cp_wait<0>();
        __syncthreads();

        if (kt == 0) {
#pragma unroll
            for (int kc = 0; kc < 4; kc++)
                ldsm_x4(qa[kc], &Qs[r0 + a_row][kc * 16 + a_col]);
        }

        if (kt + 1 < TTXT / 64) {
            int nxt = cur ^ 1;
            int kb = (kt + 1) * 64;
#pragma unroll
            for (int p = 0; p < 2; p++) {
                int r = ar + p * 32;
                cp_async16(&Ks[nxt][r][ac8], &Kg[(size_t)(kb + r) * 64 + ac8]);
                cp_async16(&Vs[nxt][r][ac8], &Vg[(size_t)r * TTXT + kb + ac8]);
            }
            cp_commit();
        }

        // S = Q K^T  (already in log2 domain — Q pre-scaled)
        float sc[8][4] = {};
#pragma unroll
        for (int kc = 0; kc < 4; kc++) {
#pragma unroll
            for (int np = 0; np < 4; np++) {
                uint32_t bb[4];
                ldsm_x4(bb, &Ks[cur][np * 16 + b_row][kc * 16 + b_col]);
                mma_bf16(sc[2 * np], qa[kc], bb);
                mma_bf16(sc[2 * np + 1], qa[kc], bb + 2);
            }
        }

        // p = 2^(s + maskbias); masked -> -inf -> 0. Packs as f16 A-frag.
        const float* Mt = Ms + kt * 64;
        uint32_t pa[4][4];
#pragma unroll
        for (int kc = 0; kc < 4; kc++) {
            float mbA0 = Mt[kc * 16 + 2 * tig], mbA1 = Mt[kc * 16 + 2 * tig + 1];
            float mbB0 = Mt[kc * 16 + 8 + 2 * tig], mbB1 = Mt[kc * 16 + 8 + 2 * tig + 1];
            pa[kc][0] = h2ex2(packh2(sc[2 * kc][0] + mbA0, sc[2 * kc][1] + mbA1));
            pa[kc][1] = h2ex2(packh2(sc[2 * kc][2] + mbA0, sc[2 * kc][3] + mbA1));
            pa[kc][2] = h2ex2(packh2(sc[2 * kc + 1][0] + mbB0, sc[2 * kc + 1][1] + mbB1));
            pa[kc][3] = h2ex2(packh2(sc[2 * kc + 1][2] + mbB0, sc[2 * kc + 1][3] + mbB1));
        }

        // O += P V  (f16 mma; V^T in smem);  l += P . 1
#pragma unroll
        for (int kc = 0; kc < 4; kc++) {
#pragma unroll
            for (int np = 0; np < 4; np++) {
                uint32_t vb[4];
                ldsm_x4(vb, &Vs[cur][np * 16 + b_row][kc * 16 + b_col]);
                mma_f16(oc[2 * np], pa[kc], vb);
                mma_f16(oc[2 * np + 1], pa[kc], vb + 2);
            }
            mma_f16(oc_l, pa[kc], b_ones);
        }
    }

    float lv0 = __shfl_sync(~0u, oc_l[0], lane & ~3);
    float lv1 = __shfl_sync(~0u, oc_l[2], lane & ~3);
    float inv0 = 1.f / lv0, inv1 = 1.f / lv1;
    int tg = qt * 128 + r0 + g;
    bf16* Ob = g_Ob + (size_t)b * TQPAD * TDm + h * 64;
#pragma unroll
    for (int ns = 0; ns < 8; ns++) {
        int c = ns * 8 + 2 * tig;
        *(uint32_t*)&Ob[(size_t)tg * TDm + c] =
            packbf2(oc[ns][0] * inv0, oc[ns][1] * inv0);
        *(uint32_t*)&Ob[(size_t)(tg + 8) * TDm + c] =
            packbf2(oc[ns][2] * inv1, oc[ns][3] * inv1);
    }
}

// ---------------------------------------------------------------------------
extern "C" void kernel_launch(void* const* d_in, const int* in_sizes, int n_in,
                              void* d_out, int out_size)
{
    const float* x     = (const float*)d_in[0];
    const float* temb  = (const float*)d_in[1];
    const float* lmask = (const float*)d_in[2];
    const int*   tmask = (const int*)d_in[3];
    const float* Wq    = (const float*)d_in[4];
    const float* bq    = (const float*)d_in[5];
    const float* Wk    = (const float*)d_in[6];
    const float* bk    = (const float*)d_in[7];
    const float* Wv    = (const float*)d_in[8];
    const float* bv    = (const float*)d_in[9];
    const float* Wo    = (const float*)d_in[10];
    const float* bo    = (const float*)d_in[11];
    const float* theta = (const float*)d_in[12];
    const float* inc   = (const float*)d_in[13];
    float* out = (float*)d_out;

    cudaFuncSetAttribute(proj_mma, cudaFuncAttributeMaxDynamicSharedMemorySize,
                         GEMM_SMEM);
    cudaFuncSetAttribute(oproj_mma, cudaFuncAttributeMaxDynamicSharedMemorySize,
                         OPROJ_SMEM);
    cudaFuncSetAttribute(attn_mma, cudaFuncAttributeMaxDynamicSharedMemorySize,
                         ATT_SMEM);

    transpose_bf<<<dim3(TQPAD / 32, CHN / 32, Bsz), dim3(32, 8)>>>(
        x, CHN, TLAT, TQPAD, 0);
    transpose_bf<<<dim3(TTXT / 32, TDm / 32, Bsz), dim3(32, 8)>>>(
        temb, TDm, TTXT, TTXT, 1);
    conv_weights<<<(TDm * CHN + 255) / 256, 256>>>(Wq, Wk, Wv, Wo);

    proj_mma<<<dim3(TQPAD / 128, NH / 2, Bsz), 256, GEMM_SMEM>>>(
        bq, theta, inc, TQPAD, TLAT, CHN, 1.f / (float)TLAT, 0);
    proj_mma<<<dim3(TTXT / 128, NH / 2, Bsz), 256, GEMM_SMEM>>>(
        bk, theta, inc, TTXT, TTXT, TDm, 1.f / (float)TTXT, 1);
    proj_mma<<<dim3(TTXT / 128, NH / 2, Bsz), 256, GEMM_SMEM>>>(
        bv, theta, inc, TTXT, TTXT, TDm, 1.f / (float)TTXT, 2);

    attn_mma<<<dim3(TQPAD / 128, NH, Bsz), 256, ATT_SMEM>>>(tmask);

    oproj_mma<<<dim3(TQPAD / 128, CHN / 64, Bsz), 256, OPROJ_SMEM>>>(
        x, bo, lmask, out);
}

// round 17
// speedup vs baseline: 1.6186x; 1.0758x over previous
#include <cuda_runtime.h>
#include <cuda_bf16.h>
#include <cuda_fp16.h>
#include <math.h>
#include <stdint.h>

typedef __nv_bfloat16 bf16;

#define Bsz 64
#define CHN 512
#define TDm 256
#define NH 4
#define DHd 64
#define TLAT 1000
#define TQPAD 1024
#define TTXT 512
// 1/sqrt(TD)=0.0625 folded with log2(e): applied to Q at projection time
#define SCALE_L2E 0.09016844f

// ---------------- scratch (device globals; allocation-free) ----------------
__device__ bf16 g_xT[(size_t)Bsz * TQPAD * CHN];
__device__ bf16 g_tT[(size_t)Bsz * TTXT * TDm];
__device__ bf16 g_Qb[(size_t)Bsz * NH * TQPAD * DHd];    // pre-scaled by SCALE_L2E
__device__ bf16 g_Kb[(size_t)Bsz * NH * TTXT * DHd];
__device__ __half g_Vh[(size_t)Bsz * NH * TTXT * DHd];   // fp16 V, [key][dh]
__device__ bf16 g_Ob[(size_t)Bsz * TQPAD * TDm];
__device__ bf16 g_Wqb[TDm * CHN];
__device__ bf16 g_Wkb[TDm * TDm];
__device__ bf16 g_Wvb[TDm * TDm];
__device__ bf16 g_Wob[CHN * TDm];
__device__ int  g_idx[Bsz * TTXT];   // compacted valid-key indices per batch
__device__ int  g_nv[Bsz];           // valid-key counts

// ---------------------------------------------------------------------------
__device__ __forceinline__ void mma_bf16(float c[4], const uint32_t a[4],
                                         const uint32_t b[2]) {
    asm volatile(
        "mma.sync.aligned.m16n8k16.row.col.f32.bf16.bf16.f32 "
        "{%0,%1,%2,%3}, {%4,%5,%6,%7}, {%8,%9}, {%0,%1,%2,%3};\n"
        : "+f"(c[0]), "+f"(c[1]), "+f"(c[2]), "+f"(c[3])
        : "r"(a[0]), "r"(a[1]), "r"(a[2]), "r"(a[3]), "r"(b[0]), "r"(b[1]));
}
__device__ __forceinline__ void mma_f16(float c[4], const uint32_t a[4],
                                        const uint32_t b[2]) {
    asm volatile(
        "mma.sync.aligned.m16n8k16.row.col.f32.f16.f16.f32 "
        "{%0,%1,%2,%3}, {%4,%5,%6,%7}, {%8,%9}, {%0,%1,%2,%3};\n"
        : "+f"(c[0]), "+f"(c[1]), "+f"(c[2]), "+f"(c[3])
        : "r"(a[0]), "r"(a[1]), "r"(a[2]), "r"(a[3]), "r"(b[0]), "r"(b[1]));
}
__device__ __forceinline__ uint32_t packbf2(float lo, float hi) {
    uint32_t r;
    asm("cvt.rn.bf16x2.f32 %0, %1, %2;" : "=r"(r) : "f"(hi), "f"(lo));
    return r;
}
__device__ __forceinline__ uint32_t packh2(float lo, float hi) {
    uint32_t r;
    asm("cvt.rn.f16x2.f32 %0, %1, %2;" : "=r"(r) : "f"(hi), "f"(lo));
    return r;
}
__device__ __forceinline__ uint32_t h2ex2(uint32_t v) {
    uint32_t r;
    asm("ex2.approx.f16x2 %0, %1;" : "=r"(r) : "r"(v));
    return r;
}
__device__ __forceinline__ void ldsm_x4(uint32_t r[4], const void* p) {
    uint32_t a = (uint32_t)__cvta_generic_to_shared(p);
    asm volatile(
        "ldmatrix.sync.aligned.m8n8.x4.shared.b16 {%0,%1,%2,%3}, [%4];"
        : "=r"(r[0]), "=r"(r[1]), "=r"(r[2]), "=r"(r[3]) : "r"(a));
}
__device__ __forceinline__ void ldsm_x4_t(uint32_t r[4], const void* p) {
    uint32_t a = (uint32_t)__cvta_generic_to_shared(p);
    asm volatile(
        "ldmatrix.sync.aligned.m8n8.x4.trans.shared.b16 {%0,%1,%2,%3}, [%4];"
        : "=r"(r[0]), "=r"(r[1]), "=r"(r[2]), "=r"(r[3]) : "r"(a));
}
__device__ __forceinline__ void cp_async16(void* dst, const void* src) {
    uint32_t d = (uint32_t)__cvta_generic_to_shared(dst);
    asm volatile("cp.async.ca.shared.global [%0], [%1], 16;" :: "r"(d), "l"(src));
}
__device__ __forceinline__ void cp_commit() {
    asm volatile("cp.async.commit_group;");
}
template <int N>
__device__ __forceinline__ void cp_wait() {
    asm volatile("cp.async.wait_group %0;" :: "n"(N));
}

// ---------------------------------------------------------------------------
// valid-key compaction (order-irrelevant: softmax is a sum over keys)
// ---------------------------------------------------------------------------
__global__ void __launch_bounds__(256) build_idx(const int* __restrict__ tmask)
{
    __shared__ int cnt;
    const int b = blockIdx.x;
    if (threadIdx.x == 0) cnt = 0;
    __syncthreads();
    for (int j = threadIdx.x; j < TTXT; j += 256) {
        if (tmask[b * TTXT + j] != 0) {
            int p = atomicAdd(&cnt, 1);
            g_idx[b * TTXT + p] = j;
        }
    }
    __syncthreads();
    if (threadIdx.x == 0) g_nv[b] = cnt;
}

// ---------------------------------------------------------------------------
// transpose+convert, vectorized stores (2 bf16 per STG.32)
// ---------------------------------------------------------------------------
__global__ void __launch_bounds__(256) transpose_bf(
    const float* __restrict__ in, int D1, int D2, int D2pad, int dst)
{
    __shared__ float tile[32][33];
    const int b = blockIdx.z;
    const int j0 = blockIdx.x * 32;
    const int i0 = blockIdx.y * 32;
    const int tx = threadIdx.x, ty = threadIdx.y;
    const float* inb = in + (size_t)b * D1 * D2;
#pragma unroll
    for (int p = 0; p < 4; p++) {
        int r = i0 + ty + p * 8;
        int j = j0 + tx;
        tile[ty + p * 8][tx] = (j < D2) ? inb[(size_t)r * D2 + j] : 0.f;
    }
    __syncthreads();
    bf16* out = (dst == 0) ? g_xT : g_tT;
    bf16* outb = out + (size_t)b * D2pad * D1;
    const int ix = (tx & 15) * 2;
    const int jq = (tx >> 4);
#pragma unroll
    for (int p = 0; p < 4; p++) {
        int jj = ty + p * 8 + jq * 16;
        int j = j0 + (jj & 31);
        *(uint32_t*)&outb[(size_t)j * D1 + i0 + ix] =
            packbf2(tile[ix][jj & 31], tile[ix + 1][jj & 31]);
    }
}

__global__ void __launch_bounds__(256) conv_weights(
    const float* __restrict__ Wq, const float* __restrict__ Wk,
    const float* __restrict__ Wv, const float* __restrict__ Wo)
{
    int i = blockIdx.x * 256 + threadIdx.x;
    if (i < TDm * CHN) g_Wqb[i] = __float2bfloat16(Wq[i]);
    if (i < TDm * TDm) {
        g_Wkb[i] = __float2bfloat16(Wk[i]);
        g_Wvb[i] = __float2bfloat16(Wv[i]);
    }
    if (i < CHN * TDm) g_Wob[i] = __float2bfloat16(Wo[i]);
}

// ---------------------------------------------------------------------------
// GEMM core 128x128: K chunks of 64, 2-stage cp.async, ONE sync per k-tile.
// ---------------------------------------------------------------------------
#define GEMM_SMEM 73728

__device__ __forceinline__ void gemm128x128(
    char* sm, const bf16* Ab, const bf16* Bb, int Kdim, int tid)
{
    bf16 (*As)[128][72] = (bf16(*)[128][72])sm;
    bf16 (*Bs)[128][72] = (bf16(*)[128][72])(sm + 2 * 128 * 72 * 2);
    float (*Cs)[133]    = (float(*)[133])sm;

    const int wid = tid >> 5, lane = tid & 31;
    const int g = lane >> 2, tig = lane & 3;
    const int m0 = (wid >> 1) * 32, n0 = (wid & 1) * 64;

    const int a_row = (lane & 7) + ((lane >> 3) & 1) * 8;
    const int a_col = (lane >> 4) * 8;
    const int b_row = ((lane >> 4) & 1) * 8 + (lane & 7);
    const int b_col = ((lane >> 3) & 1) * 8;

    const int fr = tid >> 3, fc8 = (tid & 7) * 8;
    const int KT = Kdim >> 6;

#pragma unroll
    for (int p = 0; p < 4; p++) {
        int r = fr + p * 32;
        cp_async16(&As[0][r][fc8], &Ab[(size_t)r * Kdim + fc8]);
        cp_async16(&Bs[0][r][fc8], &Bb[(size_t)r * Kdim + fc8]);
    }
    cp_commit();

    float acc[2][8][4] = {};

    for (int kt = 0; kt < KT; kt++) {
        int cur = kt & 1;
        cp_wait<0>();
        __syncthreads();
        if (kt + 1 < KT) {
            int nxt = cur ^ 1;
            int k0 = (kt + 1) << 6;
#pragma unroll
            for (int p = 0; p < 4; p++) {
                int r = fr + p * 32;
                cp_async16(&As[nxt][r][fc8], &Ab[(size_t)r * Kdim + k0 + fc8]);
                cp_async16(&Bs[nxt][r][fc8], &Bb[(size_t)r * Kdim + k0 + fc8]);
            }
            cp_commit();
        }

#pragma unroll
        for (int kc = 0; kc < 4; kc++) {
            uint32_t am[2][4];
            ldsm_x4(am[0], &As[cur][m0 + a_row][kc * 16 + a_col]);
            ldsm_x4(am[1], &As[cur][m0 + 16 + a_row][kc * 16 + a_col]);
#pragma unroll
            for (int np = 0; np < 4; np++) {
                uint32_t bb[4];
                ldsm_x4(bb, &Bs[cur][n0 + np * 16 + b_row][kc * 16 + b_col]);
                mma_bf16(acc[0][2 * np], am[0], bb);
                mma_bf16(acc[0][2 * np + 1], am[0], bb + 2);
                mma_bf16(acc[1][2 * np], am[1], bb);
                mma_bf16(acc[1][2 * np + 1], am[1], bb + 2);
            }
        }
    }
    __syncthreads();   // protect Cs overlay of As/Bs

#pragma unroll
    for (int ms = 0; ms < 2; ms++)
#pragma unroll
        for (int ns = 0; ns < 8; ns++) {
            int r = m0 + ms * 16 + g;
            int c = n0 + ns * 8 + 2 * tig;
            Cs[r][c]         = acc[ms][ns][0];
            Cs[r][c + 1]     = acc[ms][ns][1];
            Cs[r + 8][c]     = acc[ms][ns][2];
            Cs[r + 8][c + 1] = acc[ms][ns][3];
        }
    __syncthreads();
}

// ---------------------------------------------------------------------------
// Projection: CTA = 128 t x 2 heads. mode 0=Q(rope, pre-scaled) 1=K(rope)
// 2=V(f16, natural [key][dh])
// ---------------------------------------------------------------------------
__global__ void __launch_bounds__(256) proj_mma(
    const float* __restrict__ bias, const float* __restrict__ theta,
    const float* __restrict__ inc, int Mpad, int M, int Kdim,
    float inv_len, int mode)
{
    extern __shared__ __align__(16) char sm[];
    float (*Cs)[133] = (float(*)[133])sm;

    const int b = blockIdx.z;
    const int h0 = blockIdx.y * 2;
    const int t0 = blockIdx.x * 128;
    const int tid = threadIdx.x;

    const bf16* A = (mode == 0) ? g_xT : g_tT;
    const bf16* W = (mode == 0) ? g_Wqb : (mode == 1) ? g_Wkb : g_Wvb;
    const bf16* Ab = A + ((size_t)b * Mpad + t0) * Kdim;
    const bf16* Wb = W + (size_t)(h0 * 64) * Kdim;

    gemm128x128(sm, Ab, Wb, Kdim, tid);

    const int th = tid >> 1;
    const int side = tid & 1;
    const int h = h0 + side;
    const int t = t0 + th;

    if (mode < 2) {
        const float oscale = (mode == 0) ? SCALE_L2E : 1.f;
        bf16* orow = ((mode == 0) ? g_Qb : g_Kb) +
                     ((size_t)(b * NH + h) * Mpad + t) * 64;
        if (t < M) {
            float pos = inc[t] * inv_len;
            const float* bs = bias + h * 64;
            float o[64];
#pragma unroll
            for (int jj = 0; jj < 32; jj++) {
                float x1 = Cs[th][side * 64 + jj] + bs[jj];
                float x2 = Cs[th][side * 64 + 32 + jj] + bs[32 + jj];
                float sv, cv;
                __sincosf(pos * theta[jj], &sv, &cv);
                o[jj] = (x1 * cv - x2 * sv) * oscale;
                o[32 + jj] = (x1 * sv + x2 * cv) * oscale;
            }
            uint32_t pk[32];
#pragma unroll
            for (int m = 0; m < 32; m++) pk[m] = packbf2(o[2 * m], o[2 * m + 1]);
#pragma unroll
            for (int q = 0; q < 8; q++)
                *(uint4*)&orow[q * 8] = *(uint4*)&pk[q * 4];
        } else {
            uint4 z = {0, 0, 0, 0};
#pragma unroll
            for (int q = 0; q < 8; q++) *(uint4*)&orow[q * 8] = z;
        }
    } else {
        // V: fp16, natural [key][dh] rows
        __half* orow = g_Vh + ((size_t)(b * NH + h) * TTXT + t) * 64;
        const float* bs = bias + h * 64;
        uint32_t pk[32];
#pragma unroll
        for (int m = 0; m < 32; m++)
            pk[m] = packh2(Cs[th][side * 64 + 2 * m] + bs[2 * m],
                           Cs[th][side * 64 + 2 * m + 1] + bs[2 * m + 1]);
#pragma unroll
        for (int q = 0; q < 8; q++)
            *(uint4*)&orow[q * 8] = *(uint4*)&pk[q * 4];
    }
}

// ---------------------------------------------------------------------------
// Output projection (R10): CTA 128 t x 64 c; single-sync; +res/bias/mask.
// ---------------------------------------------------------------------------
#define OPROJ_SMEM 55296

__global__ void __launch_bounds__(256) oproj_mma(
    const float* __restrict__ x, const float* __restrict__ bo,
    const float* __restrict__ lmask, float* __restrict__ out)
{
    extern __shared__ __align__(16) char smraw[];
    bf16 (*As)[128][72] = (bf16(*)[128][72])smraw;
    bf16 (*Bs)[64][72]  = (bf16(*)[64][72])(smraw + 2 * 128 * 72 * 2);
    float (*Cs)[65]     = (float(*)[65])smraw;

    const int b = blockIdx.z;
    const int t0 = blockIdx.x * 128;
    const int c0 = blockIdx.y * 64;
    const int tid = threadIdx.x;
    const int wid = tid >> 5, lane = tid & 31;
    const int g = lane >> 2, tig = lane & 3;
    const int m0 = (wid >> 1) * 32, n0 = (wid & 1) * 32;

    const int a_row = (lane & 7) + ((lane >> 3) & 1) * 8;
    const int a_col = (lane >> 4) * 8;
    const int b_row = ((lane >> 4) & 1) * 8 + (lane & 7);
    const int b_col = ((lane >> 3) & 1) * 8;

    const bf16* Ab = g_Ob + ((size_t)b * TQPAD + t0) * TDm;
    const bf16* Wb = g_Wob + (size_t)c0 * TDm;

    const int ar = tid >> 3, ac8 = (tid & 7) * 8;
    const int KT = TDm >> 6;

#pragma unroll
    for (int p = 0; p < 4; p++)
        cp_async16(&As[0][ar + p * 32][ac8], &Ab[(size_t)(ar + p * 32) * TDm + ac8]);
#pragma unroll
    for (int p = 0; p < 2; p++)
        cp_async16(&Bs[0][ar + p * 32][ac8], &Wb[(size_t)(ar + p * 32) * TDm + ac8]);
    cp_commit();

    float acc[2][4][4] = {};

    for (int kt = 0; kt < KT; kt++) {
        int cur = kt & 1;
        cp_wait<0>();
        __syncthreads();
        if (kt + 1 < KT) {
            int nxt = cur ^ 1;
            int k0 = (kt + 1) << 6;
#pragma unroll
            for (int p = 0; p < 4; p++)
                cp_async16(&As[nxt][ar + p * 32][ac8],
                           &Ab[(size_t)(ar + p * 32) * TDm + k0 + ac8]);
#pragma unroll
            for (int p = 0; p < 2; p++)
                cp_async16(&Bs[nxt][ar + p * 32][ac8],
                           &Wb[(size_t)(ar + p * 32) * TDm + k0 + ac8]);
            cp_commit();
        }

#pragma unroll
        for (int kc = 0; kc < 4; kc++) {
            uint32_t am[2][4];
            ldsm_x4(am[0], &As[cur][m0 + a_row][kc * 16 + a_col]);
            ldsm_x4(am[1], &As[cur][m0 + 16 + a_row][kc * 16 + a_col]);
#pragma unroll
            for (int np = 0; np < 2; np++) {
                uint32_t bb[4];
                ldsm_x4(bb, &Bs[cur][n0 + np * 16 + b_row][kc * 16 + b_col]);
                mma_bf16(acc[0][2 * np], am[0], bb);
                mma_bf16(acc[0][2 * np + 1], am[0], bb + 2);
                mma_bf16(acc[1][2 * np], am[1], bb);
                mma_bf16(acc[1][2 * np + 1], am[1], bb + 2);
            }
        }
    }
    __syncthreads();   // protect Cs overlay

#pragma unroll
    for (int ms = 0; ms < 2; ms++)
#pragma unroll
        for (int ns = 0; ns < 4; ns++) {
            int r = m0 + ms * 16 + g;
            int c = n0 + ns * 8 + 2 * tig;
            Cs[r][c]         = acc[ms][ns][0];
            Cs[r][c + 1]     = acc[ms][ns][1];
            Cs[r + 8][c]     = acc[ms][ns][2];
            Cs[r + 8][c + 1] = acc[ms][ns][3];
        }
    __syncthreads();

    int tt = tid & 127;
    int t = t0 + tt;
    if (t < TLAT) {
        float lm = lmask[(size_t)b * TLAT + t];
        int cb = (tid >> 7) * 32;
#pragma unroll
        for (int p = 0; p < 32; p++) {
            int cc = cb + p;
            int c = c0 + cc;
            size_t idx = ((size_t)b * CHN + c) * TLAT + t;
            out[idx] = (x[idx] + bo[c] + Cs[tt][cc]) * lm;
        }
    }
}

// ---------------------------------------------------------------------------
// FA attention over COMPACTED valid keys: gathered K/V rows via g_idx, loop
// ceil(nv/64) tiles (~half of 8). Static-max softmax (p = 2^(s + tailbias)),
// f16x2 ex2, f16 PV with ldmatrix.trans on natural-layout V, l via ones-MMA.
// ---------------------------------------------------------------------------
#define ATT_SMEM ((128 + 256) * 72 * 2 + 512 * 4)

__global__ void __launch_bounds__(256) attn_mma()
{
    extern __shared__ __align__(16) char smraw[];
    bf16 (*Qs)[72]        = (bf16(*)[72])smraw;
    bf16 (*Ks)[64][72]    = (bf16(*)[64][72])(smraw + 128 * 72 * 2);
    __half (*Vs)[64][72]  = (__half(*)[64][72])(smraw + (128 + 128) * 72 * 2);
    float* Ms             = (float*)(smraw + (128 + 256) * 72 * 2);

    const int qt = blockIdx.x, h = blockIdx.y, b = blockIdx.z;
    const int tid = threadIdx.x;
    const int wid = tid >> 5, lane = tid & 31;
    const int g = lane >> 2, tig = lane & 3;
    const int r0 = wid * 16;

    const int a_row = (lane & 7) + ((lane >> 3) & 1) * 8;
    const int a_col = (lane >> 4) * 8;
    const int b_row = ((lane >> 4) & 1) * 8 + (lane & 7);
    const int b_col = ((lane >> 3) & 1) * 8;
    // trans-ldsm addressing for V [key][dh]: rows over k(keys), cols over n(dh)
    const int tv_row = ((lane >> 3) & 1) * 8 + (lane & 7);
    const int tv_col = ((lane >> 4) & 1) * 8;

    const bf16* Qg = g_Qb + ((size_t)(b * NH + h) * TQPAD + qt * 128) * 64;
    const bf16* Kg = g_Kb + (size_t)(b * NH + h) * TTXT * 64;
    const __half* Vg = g_Vh + (size_t)(b * NH + h) * TTXT * 64;
    const int* idxb = g_idx + b * TTXT;
    const int nv = g_nv[b];
    const int nkt = (nv + 63) >> 6;

    const int ar = tid >> 3, ac8 = (tid & 7) * 8;
    const float NEGINF = __int_as_float(0xff800000);

    // prologue: Q + gathered K/V tile 0 + tail-bias array
#pragma unroll
    for (int p = 0; p < 4; p++)
        cp_async16(&Qs[ar + p * 32][ac8], &Qg[(size_t)(ar + p * 32) * 64 + ac8]);
#pragma unroll
    for (int p = 0; p < 2; p++) {
        int r = ar + p * 32;
        int key = (r < nv) ? idxb[r] : 0;
        cp_async16(&Ks[0][r][ac8], &Kg[(size_t)key * 64 + ac8]);
        cp_async16(&Vs[0][r][ac8], &Vg[(size_t)key * 64 + ac8]);
    }
    cp_commit();
#pragma unroll
    for (int p = 0; p < 2; p++) {
        int j = tid + p * 256;
        Ms[j] = (j < nv) ? 0.f : NEGINF;
    }

    const uint32_t bone = (g == 0) ? 0x3C003C00u : 0u;
    uint32_t b_ones[2] = {bone, bone};

    float oc[8][4] = {};
    float oc_l[4] = {};
    uint32_t qa[4][4];

    for (int kt = 0; kt < nkt; kt++) {
        int cur = kt & 1;
        cp_wait<0>();
        __syncthreads();

        if (kt == 0) {
#pragma unroll
            for (int kc = 0; kc < 4; kc++)
                ldsm_x4(qa[kc], &Qs[r0 + a_row][kc * 16 + a_col]);
        }

        if (kt + 1 < nkt) {
            int nxt = cur ^ 1;
            int kb = (kt + 1) * 64;
#pragma unroll
            for (int p = 0; p < 2; p++) {
                int pos = kb + ar + p * 32;
                int key = (pos < nv) ? idxb[pos] : 0;
                cp_async16(&Ks[nxt][ar + p * 32][ac8], &Kg[(size_t)key * 64 + ac8]);
                cp_async16(&Vs[nxt][ar + p * 32][ac8], &Vg[(size_t)key * 64 + ac8]);
            }
            cp_commit();
        }

        // S = Q K^T  (log2 domain — Q pre-scaled)
        float sc[8][4] = {};
#pragma unroll
        for (int kc = 0; kc < 4; kc++) {
#pragma unroll
            for (int np = 0; np < 4; np++) {
                uint32_t bb[4];
                ldsm_x4(bb, &Ks[cur][np * 16 + b_row][kc * 16 + b_col]);
                mma_bf16(sc[2 * np], qa[kc], bb);
                mma_bf16(sc[2 * np + 1], qa[kc], bb + 2);
            }
        }

        // p = 2^(s + tailbias); tail slots -> -inf -> 0. Packs as f16 A-frag.
        const float* Mt = Ms + kt * 64;
        uint32_t pa[4][4];
#pragma unroll
        for (int kc = 0; kc < 4; kc++) {
            float mbA0 = Mt[kc * 16 + 2 * tig], mbA1 = Mt[kc * 16 + 2 * tig + 1];
            float mbB0 = Mt[kc * 16 + 8 + 2 * tig], mbB1 = Mt[kc * 16 + 8 + 2 * tig + 1];
            pa[kc][0] = h2ex2(packh2(sc[2 * kc][0] + mbA0, sc[2 * kc][1] + mbA1));
            pa[kc][1] = h2ex2(packh2(sc[2 * kc][2] + mbA0, sc[2 * kc][3] + mbA1));
            pa[kc][2] = h2ex2(packh2(sc[2 * kc + 1][0] + mbB0, sc[2 * kc + 1][1] + mbB1));
            pa[kc][3] = h2ex2(packh2(sc[2 * kc + 1][2] + mbB0, sc[2 * kc + 1][3] + mbB1));
        }

        // O += P V  (f16 mma; V natural [key][dh], trans ldsm);  l += P . 1
#pragma unroll
        for (int kc = 0; kc < 4; kc++) {
#pragma unroll
            for (int np = 0; np < 4; np++) {
                uint32_t vb[4];
                ldsm_x4_t(vb, &Vs[cur][kc * 16 + tv_row][np * 16 + tv_col]);
                mma_f16(oc[2 * np], pa[kc], vb);
                mma_f16(oc[2 * np + 1], pa[kc], vb + 2);
            }
            mma_f16(oc_l, pa[kc], b_ones);
        }
    }

    float lv0 = __shfl_sync(~0u, oc_l[0], lane & ~3);
    float lv1 = __shfl_sync(~0u, oc_l[2], lane & ~3);
    float inv0 = 1.f / lv0, inv1 = 1.f / lv1;
    int tg = qt * 128 + r0 + g;
    bf16* Ob = g_Ob + (size_t)b * TQPAD * TDm + h * 64;
#pragma unroll
    for (int ns = 0; ns < 8; ns++) {
        int c = ns * 8 + 2 * tig;
        *(uint32_t*)&Ob[(size_t)tg * TDm + c] =
            packbf2(oc[ns][0] * inv0, oc[ns][1] * inv0);
        *(uint32_t*)&Ob[(size_t)(tg + 8) * TDm + c] =
            packbf2(oc[ns][2] * inv1, oc[ns][3] * inv1);
    }
}

// ---------------------------------------------------------------------------
extern "C" void kernel_launch(void* const* d_in, const int* in_sizes, int n_in,
                              void* d_out, int out_size)
{
    const float* x     = (const float*)d_in[0];
    const float* temb  = (const float*)d_in[1];
    const float* lmask = (const float*)d_in[2];
    const int*   tmask = (const int*)d_in[3];
    const float* Wq    = (const float*)d_in[4];
    const float* bq    = (const float*)d_in[5];
    const float* Wk    = (const float*)d_in[6];
    const float* bk    = (const float*)d_in[7];
    const float* Wv    = (const float*)d_in[8];
    const float* bv    = (const float*)d_in[9];
    const float* Wo    = (const float*)d_in[10];
    const float* bo    = (const float*)d_in[11];
    const float* theta = (const float*)d_in[12];
    const float* inc   = (const float*)d_in[13];
    float* out = (float*)d_out;

    cudaFuncSetAttribute(proj_mma, cudaFuncAttributeMaxDynamicSharedMemorySize,
                         GEMM_SMEM);
    cudaFuncSetAttribute(oproj_mma, cudaFuncAttributeMaxDynamicSharedMemorySize,
                         OPROJ_SMEM);
    cudaFuncSetAttribute(attn_mma, cudaFuncAttributeMaxDynamicSharedMemorySize,
                         ATT_SMEM);

    transpose_bf<<<dim3(TQPAD / 32, CHN / 32, Bsz), dim3(32, 8)>>>(
        x, CHN, TLAT, TQPAD, 0);
    transpose_bf<<<dim3(TTXT / 32, TDm / 32, Bsz), dim3(32, 8)>>>(
        temb, TDm, TTXT, TTXT, 1);
    conv_weights<<<(TDm * CHN + 255) / 256, 256>>>(Wq, Wk, Wv, Wo);
    build_idx<<<Bsz, 256>>>(tmask);

    proj_mma<<<dim3(TQPAD / 128, NH / 2, Bsz), 256, GEMM_SMEM>>>(
        bq, theta, inc, TQPAD, TLAT, CHN, 1.f / (float)TLAT, 0);
    proj_mma<<<dim3(TTXT / 128, NH / 2, Bsz), 256, GEMM_SMEM>>>(
        bk, theta, inc, TTXT, TTXT, TDm, 1.f / (float)TTXT, 1);
    proj_mma<<<dim3(TTXT / 128, NH / 2, Bsz), 256, GEMM_SMEM>>>(
        bv, theta, inc, TTXT, TTXT, TDm, 1.f / (float)TTXT, 2);

    attn_mma<<<dim3(TQPAD / 128, NH, Bsz), 256, ATT_SMEM>>>();

    oproj_mma<<<dim3(TQPAD / 128, CHN / 64, Bsz), 256, OPROJ_SMEM>>>(
        x, bo, lmask, out);
}